// round 8
// baseline (speedup 1.0000x reference)
#include <cuda_runtime.h>

#define NN    4
#define CC    20
#define HH    64
#define WWID  2048
#define KHW   5
#define PLANE (HH * WWID)     // 131072

#define TPB   128
#define TILE  256             // output px per block, 2 px/thread
#define COLS  264             // staged cols: ww = w0-4 .. w0+259
#define NV4   (COLS / 4)      // 66 float4 per row
#define CH_PER_G   2
#define NGROUPS    (CC / CH_PER_G)           // 10
#define STAGE_FLTS (CH_PER_G * KHW * COLS)   // 2640 floats per ring stage
#define NSTAGE     3                          // 31680 B total -> 6 CTAs/SM
#define SLOTS      (CH_PER_G * KHW * NV4)    // 660 float4 copies per group
#define SLOTS_FULL 5                          // 128*5 = 640 slots
#define SLOTS_REM  (SLOTS - TPB * SLOTS_FULL) // 20 extra (threads 0..19)

__device__ __forceinline__ void cp_async16(void* smem, const void* gmem)
{
    unsigned saddr = (unsigned)__cvta_generic_to_shared(smem);
    asm volatile("cp.async.cg.shared.global [%0], [%1], 16;\n"
                 :: "r"(saddr), "l"(gmem));
}
__device__ __forceinline__ void cp_commit()
{
    asm volatile("cp.async.commit_group;\n" ::: "memory");
}
template <int N>
__device__ __forceinline__ void cp_wait()
{
    asm volatile("cp.async.wait_group %0;\n" :: "n"(N) : "memory");
}

__global__ __launch_bounds__(TPB, 6)
void lcxyz_kernel(const float* __restrict__ xyz,
                  const float* __restrict__ softmax,
                  const void* __restrict__ mask,
                  float* __restrict__ out)
{
    __shared__ float ring[NSTAGE * STAGE_FLTS];
    __shared__ int   sh_mode;

    const int t  = threadIdx.x;
    const int w0 = blockIdx.x * TILE;
    const int h  = blockIdx.y;
    const int n  = blockIdx.z;

    // ---- mask dtype detection (warp 0): 0=u8, 1=i32, 2=f32 ----
    if (t < 32) {
        const unsigned* m = (const unsigned*)mask;
        unsigned w1 = m[t], w2 = m[t + 32];
        bool i32ok = (w1 <= 1u) && (w2 <= 1u);
        bool f32ok = (w1 == 0u || w1 == 0x3F800000u) &&
                     (w2 == 0u || w2 == 0x3F800000u);
        unsigned bi = __ballot_sync(0xFFFFFFFFu, i32ok);
        unsigned bf = __ballot_sync(0xFFFFFFFFu, f32ok);
        if (t == 0) sh_mode = (bi == 0xFFFFFFFFu) ? 1 : ((bf == 0xFFFFFFFFu) ? 2 : 0);
    }

    int hrow[KHW];
#pragma unroll
    for (int r = 0; r < KHW; ++r)
        hrow[r] = min(max(h + r - 2, 0), HH - 1);

    const float* sm_base = softmax + (size_t)(n * CC) * PLANE;

    // ---- Precompute staging slots: 5 per thread + 1 extra for t<20 ----
    unsigned soff[SLOTS_FULL], goff[SLOTS_FULL];
    unsigned soffX = 0, goffX = 0;
    const bool hasX = (t < SLOTS_REM);
#pragma unroll
    for (int k = 0; k <= SLOTS_FULL; ++k) {
        int j = (k < SLOTS_FULL) ? (t + TPB * k) : (TPB * SLOTS_FULL + t);
        int ch  = j / (KHW * NV4);
        int rem = j - ch * (KHW * NV4);
        int rr  = rem / NV4;
        int i   = rem - rr * NV4;
        unsigned so = ch * (KHW * COLS) + rr * COLS + 4 * i;
        int gidx = hrow[rr] * WWID + (w0 - 4) + 4 * i;
        gidx = min(max(gidx, 0), PLANE - 4);     // edge garbage killed by gm=0
        unsigned go = ch * PLANE + gidx;
        if (k < SLOTS_FULL) { soff[k] = so; goff[k] = go; }
        else                { soffX   = so; goffX   = go; }
    }

    // ---- Prologue: prefetch groups 0 (stage 0) and 1 (stage 1) ----
#pragma unroll
    for (int k = 0; k < SLOTS_FULL; ++k)
        cp_async16(ring + soff[k], sm_base + goff[k]);
    if (hasX) cp_async16(ring + soffX, sm_base + goffX);
    cp_commit();
#pragma unroll
    for (int k = 0; k < SLOTS_FULL; ++k)
        cp_async16(ring + STAGE_FLTS + soff[k], sm_base + CH_PER_G * PLANE + goff[k]);
    if (hasX) cp_async16(ring + STAGE_FLTS + soffX, sm_base + CH_PER_G * PLANE + goffX);
    cp_commit();

    __syncthreads();    // sh_mode visible
    const int mmode = sh_mode;

    // ---- Phase 1: masked Gaussian weights for 2 adjacent pixels (direct gmem) ----
    const int wa = w0 + 2 * t;
    const int cc = 2 * t + 4;

    const float* Xx = xyz + (size_t)n * 3 * PLANE;
    const float* Xy = Xx + PLANE;
    const float* Xz = Xy + PLANE;
    const size_t mbase = (size_t)n * PLANE;
    const unsigned char* mk_u8  = (const unsigned char*)mask + mbase;
    const int*           mk_i32 = (const int*)mask + mbase;
    const float*         mk_f32 = (const float*)mask + mbase;

    const float cx0 = Xx[h * WWID + wa],     cy0 = Xy[h * WWID + wa],     cz0 = Xz[h * WWID + wa];
    const float cx1 = Xx[h * WWID + wa + 1], cy1 = Xy[h * WWID + wa + 1], cz1 = Xz[h * WWID + wa + 1];

    float gm0[25], gm1[25];
#pragma unroll
    for (int dy = 0; dy < KHW; ++dy) {
        const int hc  = hrow[dy];
        const int hh  = h + dy - 2;
        const bool hok = (hh >= 0) && (hh < HH);
        float m[6], nx[6], ny[6], nz[6];
#pragma unroll
        for (int j = 0; j < 6; ++j) {
            int wraw = wa + j - 2;
            int ww = min(max(wraw, 0), WWID - 1);
            int idx = hc * WWID + ww;
            nx[j] = Xx[idx];  ny[j] = Xy[idx];  nz[j] = Xz[idx];
            bool ok = hok && (wraw >= 0) && (wraw < WWID);
            float mv = 0.0f;
            if (ok) {
                if (mmode == 1)      mv = (float)mk_i32[idx];
                else if (mmode == 2) mv = mk_f32[idx];
                else                 mv = (float)mk_u8[idx];
            }
            m[j] = mv;
        }
#pragma unroll
        for (int dx = 0; dx < KHW; ++dx) {
            float ax = nx[dx] - cx0, ay = ny[dx] - cy0, az = nz[dx] - cz0;
            float d2a = fmaf(ax, ax, fmaf(ay, ay, az * az));
            gm0[dy*5+dx] = m[dx] * __expf(-0.5f * d2a);
            float bx = nx[dx+1] - cx1, by = ny[dx+1] - cy1, bz = nz[dx+1] - cz1;
            float d2b = fmaf(bx, bx, fmaf(by, by, bz * bz));
            gm1[dy*5+dx] = m[dx+1] * __expf(-0.5f * d2b);
        }
    }

    // ---- Phase 2: 10 groups, 3-stage ring, prefetch distance 2 ----
    float* outp = out + ((size_t)(n * CC) * HH + h) * WWID + wa;

    int s_rd = 0;              // stage holding group g
    int s_wr = 2;              // stage to fill with group g+2
    for (int g = 0; g < NGROUPS; ++g) {
        if (g < NGROUPS - 1) cp_wait<1>();   // group g landed (g+1 may be in flight)
        else                 cp_wait<0>();
        __syncthreads();                      // data visible; readers of s_wr done

        if (g + 2 < NGROUPS) {
            const float* gb = sm_base + (size_t)(g + 2) * (CH_PER_G * PLANE);
            float* buf = ring + s_wr * STAGE_FLTS;
#pragma unroll
            for (int k = 0; k < SLOTS_FULL; ++k)
                cp_async16(buf + soff[k], gb + goff[k]);
            if (hasX) cp_async16(buf + soffX, gb + goffX);
            cp_commit();
        }

        const float* B = ring + s_rd * STAGE_FLTS;
#pragma unroll
        for (int ch = 0; ch < CH_PER_G; ++ch) {
            const float* Bc = B + ch * (KHW * COLS);
            // 4 independent accumulator chains (even/odd taps per pixel)
            float a0e = 0.0f, a0o = 0.0f, a1e = 0.0f, a1o = 0.0f;
#pragma unroll
            for (int dy = 0; dy < KHW; ++dy) {
                const float* rowp = Bc + dy * COLS + (cc - 2);   // even -> 8B aligned
                float2 s01 = *(const float2*)(rowp);
                float2 s23 = *(const float2*)(rowp + 2);
                float2 s45 = *(const float2*)(rowp + 4);
                float s0 = s01.x, s1 = s01.y, s2 = s23.x,
                      s3 = s23.y, s4 = s45.x, s5 = s45.y;
                a0e = fmaf(gm0[dy*5+0], s0, a0e);  a1e = fmaf(gm1[dy*5+0], s1, a1e);
                a0o = fmaf(gm0[dy*5+1], s1, a0o);  a1o = fmaf(gm1[dy*5+1], s2, a1o);
                a0e = fmaf(gm0[dy*5+2], s2, a0e);  a1e = fmaf(gm1[dy*5+2], s3, a1e);
                a0o = fmaf(gm0[dy*5+3], s3, a0o);  a1o = fmaf(gm1[dy*5+3], s4, a1o);
                a0e = fmaf(gm0[dy*5+4], s4, a0e);  a1e = fmaf(gm1[dy*5+4], s5, a1e);
            }
            *(float2*)(outp + (size_t)(g * CH_PER_G + ch) * PLANE) =
                make_float2(a0e + a0o, a1e + a1o);
        }

        s_rd = (s_rd == NSTAGE - 1) ? 0 : s_rd + 1;
        s_wr = (s_wr == NSTAGE - 1) ? 0 : s_wr + 1;
    }
}

extern "C" void kernel_launch(void* const* d_in, const int* in_sizes, int n_in,
                              void* d_out, int out_size)
{
    const float* xyz     = (const float*)d_in[0];
    const float* softmax = (const float*)d_in[1];
    const void*  mask    = d_in[2];
    float*       out     = (float*)d_out;

    dim3 grid(WWID / TILE, HH, NN);   // (8, 64, 4) = 2048 blocks
    dim3 block(TPB);
    lcxyz_kernel<<<grid, block>>>(xyz, softmax, mask, out);
}